// round 1
// baseline (speedup 1.0000x reference)
#include <cuda_runtime.h>

#define Bsz 1024
#define Tsz 256
#define Dsz 128
#define Hsz 64
#define G4  256   // 4*H

// 256 MB scratch for x_proj[b*T + t][g]  (device global: allocation-free rule)
__device__ float g_xproj[Bsz * Tsz * G4];

// ---------------------------------------------------------------------------
// Kernel A: x_proj = x @ W_ih^T + (b_ih + b_hh)
// M = B*T = 262144, N = 256, K = 128.  fp32 SIMT tiled GEMM 128x128x16.
// ---------------------------------------------------------------------------
#define BM 128
#define BN 128
#define BK 16

__global__ __launch_bounds__(256, 2) void xproj_gemm(
    const float* __restrict__ x,
    const float* __restrict__ Wih,
    const float* __restrict__ bih,
    const float* __restrict__ bhh)
{
    __shared__ float As[BK][BM + 4];
    __shared__ float Bs[BK][BN + 4];

    const int tid = threadIdx.x;
    const int bm  = blockIdx.x * BM;
    const int bn  = blockIdx.y * BN;
    const int tx  = tid & 15;
    const int ty  = tid >> 4;

    float acc[8][8];
#pragma unroll
    for (int i = 0; i < 8; i++)
#pragma unroll
        for (int j = 0; j < 8; j++) acc[i][j] = 0.f;

    for (int kk = 0; kk < Dsz; kk += BK) {
        // Load A tile (128 rows x 16 k) : 512 float4, 2 per thread, store transposed
#pragma unroll
        for (int l = 0; l < 2; l++) {
            int i   = tid + l * 256;
            int row = i >> 2;
            int c4  = i & 3;
            float4 v = *(const float4*)(x + (size_t)(bm + row) * Dsz + kk + c4 * 4);
            As[c4 * 4 + 0][row] = v.x;
            As[c4 * 4 + 1][row] = v.y;
            As[c4 * 4 + 2][row] = v.z;
            As[c4 * 4 + 3][row] = v.w;
        }
        // Load B tile (128 gate-rows x 16 k), store transposed
#pragma unroll
        for (int l = 0; l < 2; l++) {
            int i   = tid + l * 256;
            int row = i >> 2;
            int c4  = i & 3;
            float4 v = *(const float4*)(Wih + (size_t)(bn + row) * Dsz + kk + c4 * 4);
            Bs[c4 * 4 + 0][row] = v.x;
            Bs[c4 * 4 + 1][row] = v.y;
            Bs[c4 * 4 + 2][row] = v.z;
            Bs[c4 * 4 + 3][row] = v.w;
        }
        __syncthreads();

#pragma unroll
        for (int k = 0; k < BK; k++) {
            float4 a0 = *(const float4*)&As[k][ty * 8];
            float4 a1 = *(const float4*)&As[k][ty * 8 + 4];
            float4 b0 = *(const float4*)&Bs[k][tx * 8];
            float4 b1 = *(const float4*)&Bs[k][tx * 8 + 4];
            float a[8] = {a0.x, a0.y, a0.z, a0.w, a1.x, a1.y, a1.z, a1.w};
            float b[8] = {b0.x, b0.y, b0.z, b0.w, b1.x, b1.y, b1.z, b1.w};
#pragma unroll
            for (int i = 0; i < 8; i++)
#pragma unroll
                for (int j = 0; j < 8; j++) acc[i][j] += a[i] * b[j];
        }
        __syncthreads();
    }

    float bias[8];
#pragma unroll
    for (int j = 0; j < 8; j++) {
        int g = bn + tx * 8 + j;
        bias[j] = bih[g] + bhh[g];
    }

#pragma unroll
    for (int i = 0; i < 8; i++) {
        int m = bm + ty * 8 + i;
        float* orow = g_xproj + (size_t)m * G4 + bn + tx * 8;
        float4 v0 = make_float4(acc[i][0] + bias[0], acc[i][1] + bias[1],
                                acc[i][2] + bias[2], acc[i][3] + bias[3]);
        float4 v1 = make_float4(acc[i][4] + bias[4], acc[i][5] + bias[5],
                                acc[i][6] + bias[6], acc[i][7] + bias[7]);
        *(float4*)(orow)     = v0;
        *(float4*)(orow + 4) = v1;
    }
}

// ---------------------------------------------------------------------------
// Kernel B: LSTM recurrence over T steps + fused MLP head.
// 128 blocks x 256 threads, NB=8 batch rows per block.
// Thread g keeps W_hh[g][0..63] in registers; h lives in shared (broadcast LDS).
// ---------------------------------------------------------------------------
#define NB 8

__device__ __forceinline__ float sigm(float v) {
    return __fdividef(1.f, 1.f + __expf(-v));
}
__device__ __forceinline__ float tanh_f(float v) {
    return 1.f - __fdividef(2.f, __expf(2.f * v) + 1.f);
}

__global__ __launch_bounds__(256, 1) void lstm_rec(
    const float* __restrict__ Whh,
    const float* __restrict__ W1, const float* __restrict__ b1,
    const float* __restrict__ W2, const float* __restrict__ b2,
    float* __restrict__ out)
{
    __shared__ float h_sh[NB][Hsz];
    __shared__ float gs[NB][G4];

    const int tid = threadIdx.x;     // tid == gate index g (0..255)
    const int r0  = blockIdx.x * NB; // first batch row handled by this block

    // W_hh row for this gate, register-resident
    float w[Hsz];
#pragma unroll
    for (int k = 0; k < Hsz; k++) w[k] = Whh[tid * Hsz + k];

    for (int i = tid; i < NB * Hsz; i += 256) ((float*)h_sh)[i] = 0.f;
    float cA = 0.f, cB = 0.f;
    __syncthreads();

    const int rA = tid >> 6;       // unit A: (rA, jA)
    const int jA = tid & 63;
    const int rB = rA + 4;         // unit B: (rB, jA)

    for (int t = 0; t < Tsz; t++) {
        float acc[NB];
#pragma unroll
        for (int r = 0; r < NB; r++)
            acc[r] = g_xproj[((size_t)(r0 + r) * Tsz + t) * G4 + tid];

#pragma unroll
        for (int k4 = 0; k4 < 16; k4++) {
#pragma unroll
            for (int r = 0; r < NB; r++) {
                float4 h4 = *(const float4*)&h_sh[r][k4 * 4];
                acc[r] += w[k4 * 4 + 0] * h4.x;
                acc[r] += w[k4 * 4 + 1] * h4.y;
                acc[r] += w[k4 * 4 + 2] * h4.z;
                acc[r] += w[k4 * 4 + 3] * h4.w;
            }
        }

#pragma unroll
        for (int r = 0; r < NB; r++) gs[r][tid] = acc[r];
        __syncthreads();

        // pointwise: this thread owns units (rA,jA) and (rB,jA)
        {
            float ig = sigm(gs[rA][jA]);
            float fg = sigm(gs[rA][64 + jA]);
            float gg = tanh_f(gs[rA][128 + jA]);
            float og = sigm(gs[rA][192 + jA]);
            cA = fg * cA + ig * gg;
            h_sh[rA][jA] = og * tanh_f(cA);
        }
        {
            float ig = sigm(gs[rB][jA]);
            float fg = sigm(gs[rB][64 + jA]);
            float gg = tanh_f(gs[rB][128 + jA]);
            float og = sigm(gs[rB][192 + jA]);
            cB = fg * cB + ig * gg;
            h_sh[rB][jA] = og * tanh_f(cB);
        }
        __syncthreads();
    }

    // Fused head: warp wid handles batch row (r0 + wid); lane = hidden-unit of layer1
    const int wid  = tid >> 5;
    const int lane = tid & 31;
    float y1 = b1[lane];
#pragma unroll
    for (int k = 0; k < Hsz; k++) y1 += W1[lane * Hsz + k] * h_sh[wid][k];
    y1 = fmaxf(y1, 0.f);
    float z = y1 * W2[lane];
#pragma unroll
    for (int off = 16; off > 0; off >>= 1) z += __shfl_down_sync(0xffffffffu, z, off);
    if (lane == 0) out[r0 + wid] = sigm(z + b2[0]);
}

// ---------------------------------------------------------------------------
extern "C" void kernel_launch(void* const* d_in, const int* in_sizes, int n_in,
                              void* d_out, int out_size)
{
    const float* x   = (const float*)d_in[0];
    const float* Wih = (const float*)d_in[1];
    const float* Whh = (const float*)d_in[2];
    const float* bih = (const float*)d_in[3];
    const float* bhh = (const float*)d_in[4];
    const float* W1  = (const float*)d_in[5];
    const float* b1  = (const float*)d_in[6];
    const float* W2  = (const float*)d_in[7];
    const float* b2  = (const float*)d_in[8];
    float* out = (float*)d_out;

    dim3 gemm_grid((Bsz * Tsz) / BM, G4 / BN);   // (2048, 2)
    xproj_gemm<<<gemm_grid, 256>>>(x, Wih, bih, bhh);
    lstm_rec<<<Bsz / NB, 256>>>(Whh, W1, b1, W2, b2, out);
}

// round 2
// speedup vs baseline: 1.1185x; 1.1185x over previous
#include <cuda_runtime.h>

#define Bsz 1024
#define Tsz 256
#define Dsz 128
#define Hsz 64
#define G4  256   // 4*H

// 256 MB scratch for x_proj[b*T + t][g]  (device global: allocation-free rule)
__device__ float g_xproj[Bsz * Tsz * G4];

// ---------------------------------------------------------------------------
// Kernel A: x_proj = x @ W_ih^T + (b_ih + b_hh)
// M = B*T = 262144, N = 256, K = 128.  fp32 SIMT GEMM 128x128x16, double-buffered.
// ---------------------------------------------------------------------------
#define BM 128
#define BN 128
#define BK 16
#define KITERS (Dsz / BK)   // 8

__global__ __launch_bounds__(256, 2) void xproj_gemm(
    const float* __restrict__ x,
    const float* __restrict__ Wih,
    const float* __restrict__ bih,
    const float* __restrict__ bhh)
{
    __shared__ float As[2][BK][BM + 4];
    __shared__ float Bs[2][BK][BN + 4];

    const int tid = threadIdx.x;
    const int bm  = blockIdx.x * BM;
    const int bn  = blockIdx.y * BN;
    const int tx  = tid & 15;
    const int ty  = tid >> 4;

    // per-thread LDG coords (2 A float4 + 2 B float4 per tile)
    const int r0 = (tid) >> 2;
    const int c0 = (tid) & 3;
    const int r1 = (tid + 256) >> 2;
    const int c1 = (tid + 256) & 3;

    float acc[8][8];
#pragma unroll
    for (int i = 0; i < 8; i++)
#pragma unroll
        for (int j = 0; j < 8; j++) acc[i][j] = 0.f;

    float4 ra0, ra1, rb0, rb1;

    // prologue: load tile 0
    ra0 = *(const float4*)(x   + (size_t)(bm + r0) * Dsz + c0 * 4);
    ra1 = *(const float4*)(x   + (size_t)(bm + r1) * Dsz + c1 * 4);
    rb0 = *(const float4*)(Wih + (size_t)(bn + r0) * Dsz + c0 * 4);
    rb1 = *(const float4*)(Wih + (size_t)(bn + r1) * Dsz + c1 * 4);
    {
        As[0][c0 * 4 + 0][r0] = ra0.x; As[0][c0 * 4 + 1][r0] = ra0.y;
        As[0][c0 * 4 + 2][r0] = ra0.z; As[0][c0 * 4 + 3][r0] = ra0.w;
        As[0][c1 * 4 + 0][r1] = ra1.x; As[0][c1 * 4 + 1][r1] = ra1.y;
        As[0][c1 * 4 + 2][r1] = ra1.z; As[0][c1 * 4 + 3][r1] = ra1.w;
        Bs[0][c0 * 4 + 0][r0] = rb0.x; Bs[0][c0 * 4 + 1][r0] = rb0.y;
        Bs[0][c0 * 4 + 2][r0] = rb0.z; Bs[0][c0 * 4 + 3][r0] = rb0.w;
        Bs[0][c1 * 4 + 0][r1] = rb1.x; Bs[0][c1 * 4 + 1][r1] = rb1.y;
        Bs[0][c1 * 4 + 2][r1] = rb1.z; Bs[0][c1 * 4 + 3][r1] = rb1.w;
    }
    __syncthreads();

#pragma unroll
    for (int it = 0; it < KITERS; it++) {
        const int cur = it & 1;
        const int nxt = cur ^ 1;
        if (it < KITERS - 1) {
            const int kk = (it + 1) * BK;
            ra0 = *(const float4*)(x   + (size_t)(bm + r0) * Dsz + kk + c0 * 4);
            ra1 = *(const float4*)(x   + (size_t)(bm + r1) * Dsz + kk + c1 * 4);
            rb0 = *(const float4*)(Wih + (size_t)(bn + r0) * Dsz + kk + c0 * 4);
            rb1 = *(const float4*)(Wih + (size_t)(bn + r1) * Dsz + kk + c1 * 4);
        }
#pragma unroll
        for (int k = 0; k < BK; k++) {
            float4 a0 = *(const float4*)&As[cur][k][ty * 8];
            float4 a1 = *(const float4*)&As[cur][k][ty * 8 + 4];
            float4 b0 = *(const float4*)&Bs[cur][k][tx * 8];
            float4 b1 = *(const float4*)&Bs[cur][k][tx * 8 + 4];
            float a[8] = {a0.x, a0.y, a0.z, a0.w, a1.x, a1.y, a1.z, a1.w};
            float b[8] = {b0.x, b0.y, b0.z, b0.w, b1.x, b1.y, b1.z, b1.w};
#pragma unroll
            for (int i = 0; i < 8; i++)
#pragma unroll
                for (int j = 0; j < 8; j++) acc[i][j] += a[i] * b[j];
        }
        if (it < KITERS - 1) {
            As[nxt][c0 * 4 + 0][r0] = ra0.x; As[nxt][c0 * 4 + 1][r0] = ra0.y;
            As[nxt][c0 * 4 + 2][r0] = ra0.z; As[nxt][c0 * 4 + 3][r0] = ra0.w;
            As[nxt][c1 * 4 + 0][r1] = ra1.x; As[nxt][c1 * 4 + 1][r1] = ra1.y;
            As[nxt][c1 * 4 + 2][r1] = ra1.z; As[nxt][c1 * 4 + 3][r1] = ra1.w;
            Bs[nxt][c0 * 4 + 0][r0] = rb0.x; Bs[nxt][c0 * 4 + 1][r0] = rb0.y;
            Bs[nxt][c0 * 4 + 2][r0] = rb0.z; Bs[nxt][c0 * 4 + 3][r0] = rb0.w;
            Bs[nxt][c1 * 4 + 0][r1] = rb1.x; Bs[nxt][c1 * 4 + 1][r1] = rb1.y;
            Bs[nxt][c1 * 4 + 2][r1] = rb1.z; Bs[nxt][c1 * 4 + 3][r1] = rb1.w;
            __syncthreads();
        }
    }

    float bias[8];
#pragma unroll
    for (int j = 0; j < 8; j++) {
        int g = bn + tx * 8 + j;
        bias[j] = bih[g] + bhh[g];
    }

#pragma unroll
    for (int i = 0; i < 8; i++) {
        int m = bm + ty * 8 + i;
        float* orow = g_xproj + (size_t)m * G4 + bn + tx * 8;
        float4 v0 = make_float4(acc[i][0] + bias[0], acc[i][1] + bias[1],
                                acc[i][2] + bias[2], acc[i][3] + bias[3]);
        float4 v1 = make_float4(acc[i][4] + bias[4], acc[i][5] + bias[5],
                                acc[i][6] + bias[6], acc[i][7] + bias[7]);
        *(float4*)(orow)     = v0;
        *(float4*)(orow + 4) = v1;
    }
}

// ---------------------------------------------------------------------------
// Kernel B: LSTM recurrence over T steps + fused MLP head.
// 256 blocks x 256 threads, NB=4 batch rows per block, 2 CTAs/SM.
// Thread g keeps W_hh[g][0..63] in registers; h lives in shared (broadcast LDS).
// Next timestep's x_proj is prefetched into registers during the matvec.
// ---------------------------------------------------------------------------
#define NB 4

__device__ __forceinline__ float sigm(float v) {
    return __fdividef(1.f, 1.f + __expf(-v));
}
__device__ __forceinline__ float tanh_f(float v) {
    return 1.f - __fdividef(2.f, __expf(2.f * v) + 1.f);
}

__global__ __launch_bounds__(256, 2) void lstm_rec(
    const float* __restrict__ Whh,
    const float* __restrict__ W1, const float* __restrict__ b1,
    const float* __restrict__ W2, const float* __restrict__ b2,
    float* __restrict__ out)
{
    __shared__ float h_sh[NB][Hsz];
    __shared__ float gs[NB][G4];

    const int tid = threadIdx.x;     // tid == gate index g (0..255)
    const int r0  = blockIdx.x * NB; // first batch row handled by this block

    // W_hh row for this gate, register-resident
    float w[Hsz];
#pragma unroll
    for (int k = 0; k < Hsz; k++) w[k] = Whh[tid * Hsz + k];

    for (int i = tid; i < NB * Hsz; i += 256) ((float*)h_sh)[i] = 0.f;

    // each thread owns one (row, unit) cell: 4 rows x 64 units = 256 threads
    const int rr = tid >> 6;
    const int jj = tid & 63;
    float c = 0.f;

    // prefetch xproj for t=0
    float xp[NB], xn[NB];
#pragma unroll
    for (int r = 0; r < NB; r++)
        xp[r] = g_xproj[((size_t)(r0 + r) * Tsz) * G4 + tid];

    __syncthreads();

    for (int t = 0; t < Tsz; t++) {
        // prefetch next timestep (clamped) — hides DRAM latency under matvec
        const int tn = (t + 1 < Tsz) ? t + 1 : t;
#pragma unroll
        for (int r = 0; r < NB; r++)
            xn[r] = g_xproj[((size_t)(r0 + r) * Tsz + tn) * G4 + tid];

        float acc[NB];
#pragma unroll
        for (int r = 0; r < NB; r++) acc[r] = xp[r];

#pragma unroll
        for (int k4 = 0; k4 < 16; k4++) {
#pragma unroll
            for (int r = 0; r < NB; r++) {
                float4 h4 = *(const float4*)&h_sh[r][k4 * 4];
                acc[r] += w[k4 * 4 + 0] * h4.x;
                acc[r] += w[k4 * 4 + 1] * h4.y;
                acc[r] += w[k4 * 4 + 2] * h4.z;
                acc[r] += w[k4 * 4 + 3] * h4.w;
            }
        }

#pragma unroll
        for (int r = 0; r < NB; r++) gs[r][tid] = acc[r];
        __syncthreads();

        // pointwise: this thread owns unit (rr, jj)
        {
            float ig = sigm(gs[rr][jj]);
            float fg = sigm(gs[rr][64 + jj]);
            float gg = tanh_f(gs[rr][128 + jj]);
            float og = sigm(gs[rr][192 + jj]);
            c = fg * c + ig * gg;
            h_sh[rr][jj] = og * tanh_f(c);
        }

#pragma unroll
        for (int r = 0; r < NB; r++) xp[r] = xn[r];
        __syncthreads();
    }

    // Fused head: warp wid (<NB) handles batch row (r0 + wid); lane = layer-1 unit
    const int wid  = tid >> 5;
    const int lane = tid & 31;
    if (wid < NB) {
        float y1 = b1[lane];
#pragma unroll
        for (int k = 0; k < Hsz; k++) y1 += W1[lane * Hsz + k] * h_sh[wid][k];
        y1 = fmaxf(y1, 0.f);
        float z = y1 * W2[lane];
#pragma unroll
        for (int off = 16; off > 0; off >>= 1) z += __shfl_down_sync(0xffffffffu, z, off);
        if (lane == 0) out[r0 + wid] = sigm(z + b2[0]);
    }
}

// ---------------------------------------------------------------------------
extern "C" void kernel_launch(void* const* d_in, const int* in_sizes, int n_in,
                              void* d_out, int out_size)
{
    const float* x   = (const float*)d_in[0];
    const float* Wih = (const float*)d_in[1];
    const float* Whh = (const float*)d_in[2];
    const float* bih = (const float*)d_in[3];
    const float* bhh = (const float*)d_in[4];
    const float* W1  = (const float*)d_in[5];
    const float* b1  = (const float*)d_in[6];
    const float* W2  = (const float*)d_in[7];
    const float* b2  = (const float*)d_in[8];
    float* out = (float*)d_out;

    dim3 gemm_grid((Bsz * Tsz) / BM, G4 / BN);   // (2048, 2)
    xproj_gemm<<<gemm_grid, 256>>>(x, Wih, bih, bhh);
    lstm_rec<<<Bsz / NB, 256>>>(Whh, W1, b1, W2, b2, out);
}